// round 1
// baseline (speedup 1.0000x reference)
#include <cuda_runtime.h>
#include <math.h>

#define B_   64
#define FULLN 513
#define E_   768
#define NB   32
#define H_   12
#define HD   64
#define BH   (B_ * H_)        // 768
#define E4   (E_ / 4)         // 192

// -------- scratch (device globals; no allocation allowed) --------
__device__ float g_sampled[B_ * NB * E_];   // (2048, 768)
__device__ float g_q[B_ * E_];              // (64, 768)
__device__ float g_T[BH * E_];              // (768, 768)  row = b*12+h
__device__ float g_TK[BH * E_];             // (768, 768)
__device__ float g_attn[BH * NB];           // (768, 32)
__device__ float g_US[BH * E_];             // (768, 768)
__device__ float g_U[BH * E_];              // (768, 768)
__device__ float g_ctx[B_ * E_];            // (64, 768)
__device__ float g_ao[B_ * E_];             // (64, 768)

// ----------------------------------------------------------------
// Trilinear border sample: one block per (b,p); 192 threads, float4 channels
// ----------------------------------------------------------------
__global__ void __launch_bounds__(192) sample_kernel(
    const float* __restrict__ x, const float* __restrict__ base,
    const float* __restrict__ off, float* __restrict__ out)
{
    int bp = blockIdx.x;
    int b = bp >> 5, p = bp & 31;

    float cx = fminf(fmaxf(base[p * 3 + 0] + off[bp * 3 + 0], -1.f), 1.f);
    float cy = fminf(fmaxf(base[p * 3 + 1] + off[bp * 3 + 1], -1.f), 1.f);
    float cz = fminf(fmaxf(base[p * 3 + 2] + off[bp * 3 + 2], -1.f), 1.f);

    float ix = (cx + 1.f) * 3.5f;   // (W-1)=7
    float iy = (cy + 1.f) * 3.5f;
    float iz = (cz + 1.f) * 3.5f;
    float fx = floorf(ix), fy = floorf(iy), fz = floorf(iz);
    float wx = ix - fx, wy = iy - fy, wz = iz - fz;
    int x0 = max(0, min(7, (int)fx));
    int y0 = max(0, min(7, (int)fy));
    int z0 = max(0, min(7, (int)fz));
    int x1 = min(7, x0 + 1), y1 = min(7, y0 + 1), z1 = min(7, z0 + 1);

    // row in x: 1 + ((z*8 + y)*8 + x)
    int r000 = 1 + ((z0 * 8 + y0) * 8 + x0);
    int r001 = 1 + ((z0 * 8 + y0) * 8 + x1);
    int r010 = 1 + ((z0 * 8 + y1) * 8 + x0);
    int r011 = 1 + ((z0 * 8 + y1) * 8 + x1);
    int r100 = 1 + ((z1 * 8 + y0) * 8 + x0);
    int r101 = 1 + ((z1 * 8 + y0) * 8 + x1);
    int r110 = 1 + ((z1 * 8 + y1) * 8 + x0);
    int r111 = 1 + ((z1 * 8 + y1) * 8 + x1);

    float w000 = (1.f - wz) * (1.f - wy) * (1.f - wx);
    float w001 = (1.f - wz) * (1.f - wy) * wx;
    float w010 = (1.f - wz) * wy * (1.f - wx);
    float w011 = (1.f - wz) * wy * wx;
    float w100 = wz * (1.f - wy) * (1.f - wx);
    float w101 = wz * (1.f - wy) * wx;
    float w110 = wz * wy * (1.f - wx);
    float w111 = wz * wy * wx;

    const float4* X = reinterpret_cast<const float4*>(x) + (long)b * FULLN * E4;
    int t = threadIdx.x;
    float4 s = make_float4(0.f, 0.f, 0.f, 0.f);
#define ACC(R, W) { float4 v = X[(R) * E4 + t]; \
        s.x = fmaf(W, v.x, s.x); s.y = fmaf(W, v.y, s.y); \
        s.z = fmaf(W, v.z, s.z); s.w = fmaf(W, v.w, s.w); }
    ACC(r000, w000) ACC(r001, w001) ACC(r010, w010) ACC(r011, w011)
    ACC(r100, w100) ACC(r101, w101) ACC(r110, w110) ACC(r111, w111)
#undef ACC
    reinterpret_cast<float4*>(out)[(long)bp * E4 + t] = s;
}

// ----------------------------------------------------------------
// Generic fp32 GEMM: C[m,n] = sum_k A[m,k] * (TB ? B[n,k] : B[k,n]) + bias[n]
// 64x64 tile, 256 threads, 4x4 per thread, K step 16.
// All M,N,K used are multiples of the tile, so no bounds checks.
// ----------------------------------------------------------------
template <bool TB>
__global__ void __launch_bounds__(256) sgemm_kernel(
    const float* __restrict__ A, const float* __restrict__ Bm,
    const float* __restrict__ bias, float* __restrict__ C,
    int M, int N, int K, int lda, int ldb, int ldc,
    int sAz, int sBz, int sCz, int sBiasz)
{
    __shared__ float As[16][65];
    __shared__ float Bs[16][65];
    const int tid = threadIdx.x;
    const int m0 = blockIdx.y * 64;
    const int n0 = blockIdx.x * 64;
    A  += (long)blockIdx.z * sAz;
    Bm += (long)blockIdx.z * sBz;
    C  += (long)blockIdx.z * sCz;
    const int biasOff = blockIdx.z * sBiasz;

    const int ra = tid >> 2;          // 0..63
    const int ka = (tid & 3) << 2;    // 0,4,8,12
    const int ty = tid >> 4;          // 0..15
    const int tx = tid & 15;          // 0..15

    float acc[4][4];
#pragma unroll
    for (int i = 0; i < 4; i++)
#pragma unroll
        for (int j = 0; j < 4; j++) acc[i][j] = 0.f;

    for (int k0 = 0; k0 < K; k0 += 16) {
        float4 a4 = *reinterpret_cast<const float4*>(&A[(long)(m0 + ra) * lda + k0 + ka]);
        As[ka + 0][ra] = a4.x; As[ka + 1][ra] = a4.y;
        As[ka + 2][ra] = a4.z; As[ka + 3][ra] = a4.w;
        if (TB) {
            float4 b4 = *reinterpret_cast<const float4*>(&Bm[(long)(n0 + ra) * ldb + k0 + ka]);
            Bs[ka + 0][ra] = b4.x; Bs[ka + 1][ra] = b4.y;
            Bs[ka + 2][ra] = b4.z; Bs[ka + 3][ra] = b4.w;
        } else {
            const int kb = tid >> 4;          // 0..15
            const int nb = (tid & 15) << 2;   // 0..60
            float4 b4 = *reinterpret_cast<const float4*>(&Bm[(long)(k0 + kb) * ldb + n0 + nb]);
            Bs[kb][nb + 0] = b4.x; Bs[kb][nb + 1] = b4.y;
            Bs[kb][nb + 2] = b4.z; Bs[kb][nb + 3] = b4.w;
        }
        __syncthreads();
#pragma unroll
        for (int kk = 0; kk < 16; kk++) {
            float a[4], b[4];
#pragma unroll
            for (int i = 0; i < 4; i++) a[i] = As[kk][ty * 4 + i];
#pragma unroll
            for (int j = 0; j < 4; j++) b[j] = Bs[kk][tx * 4 + j];
#pragma unroll
            for (int i = 0; i < 4; i++)
#pragma unroll
                for (int j = 0; j < 4; j++)
                    acc[i][j] = fmaf(a[i], b[j], acc[i][j]);
        }
        __syncthreads();
    }

#pragma unroll
    for (int i = 0; i < 4; i++) {
        int m = m0 + ty * 4 + i;
#pragma unroll
        for (int j = 0; j < 4; j++) {
            int n = n0 + tx * 4 + j;
            float v = acc[i][j];
            if (bias) v += bias[biasOff + n];
            C[(long)m * ldc + n] = v;
        }
    }
}

// ----------------------------------------------------------------
// scores + softmax per (b,h): scores[p] = (sampled[b,p]·TK[bh] + T[bh]·bs + q[b,h]·bk) / 8
// ----------------------------------------------------------------
__global__ void __launch_bounds__(128) scores_softmax_kernel(
    const float* __restrict__ TK, const float* __restrict__ T,
    const float* __restrict__ q, const float* __restrict__ sampled,
    const float* __restrict__ in_proj_b, const float* __restrict__ bs,
    float* __restrict__ attn)
{
    int bh = blockIdx.x;
    int b = bh / H_, h = bh % H_;
    __shared__ float tk[E_];
    __shared__ float sc[NB];
    __shared__ float red[4];
    __shared__ float cbs;
    int tid = threadIdx.x;
    int w = tid >> 5, lane = tid & 31;

    const float* TKrow = TK + (long)bh * E_;
    const float* Trow  = T + (long)bh * E_;
    float part = 0.f;
    for (int f = tid; f < E_; f += 128) {
        float t = TKrow[f];
        tk[f] = t;
        part += Trow[f] * bs[f];
    }
    if (tid < HD)
        part += q[(long)b * E_ + h * HD + tid] * in_proj_b[E_ + h * HD + tid];
#pragma unroll
    for (int o = 16; o; o >>= 1) part += __shfl_xor_sync(0xffffffffu, part, o);
    if (lane == 0) red[w] = part;
    __syncthreads();
    if (tid == 0) cbs = red[0] + red[1] + red[2] + red[3];
    __syncthreads();

    float cb = cbs;
#pragma unroll
    for (int pi = 0; pi < 8; pi++) {
        int p = w * 8 + pi;
        const float* srow = sampled + ((long)b * NB + p) * E_;
        float d = 0.f;
        for (int f = lane; f < E_; f += 32) d = fmaf(tk[f], srow[f], d);
#pragma unroll
        for (int o = 16; o; o >>= 1) d += __shfl_xor_sync(0xffffffffu, d, o);
        if (lane == 0) sc[p] = (d + cb) * 0.125f;
    }
    __syncthreads();
    if (tid < NB) {
        float s = sc[tid];
        float m = s;
#pragma unroll
        for (int o = 16; o; o >>= 1) m = fmaxf(m, __shfl_xor_sync(0xffffffffu, m, o));
        float e = expf(s - m);
        float sum = e;
#pragma unroll
        for (int o = 16; o; o >>= 1) sum += __shfl_xor_sync(0xffffffffu, sum, o);
        attn[(long)bh * NB + tid] = e / sum;
    }
}

// ----------------------------------------------------------------
// US[bh, f] = sum_p attn[bh,p] * sampled[b,p,f]
// ----------------------------------------------------------------
__global__ void __launch_bounds__(192) us_kernel(
    const float* __restrict__ attn, const float* __restrict__ sampled,
    float* __restrict__ US)
{
    int bh = blockIdx.x;
    int b = bh / H_;
    __shared__ float a[NB];
    if (threadIdx.x < NB) a[threadIdx.x] = attn[(long)bh * NB + threadIdx.x];
    __syncthreads();
    int t = threadIdx.x;
    const float4* S = reinterpret_cast<const float4*>(sampled) + (long)b * NB * E4;
    float4 acc = make_float4(0.f, 0.f, 0.f, 0.f);
#pragma unroll 8
    for (int p = 0; p < NB; p++) {
        float wv = a[p];
        float4 s = S[p * E4 + t];
        acc.x = fmaf(wv, s.x, acc.x); acc.y = fmaf(wv, s.y, acc.y);
        acc.z = fmaf(wv, s.z, acc.z); acc.w = fmaf(wv, s.w, acc.w);
    }
    reinterpret_cast<float4*>(US)[(long)bh * E4 + t] = acc;
}

// ----------------------------------------------------------------
// out[b,n,c] = attn_out[b,c] * confidence[b]   (float4 vectorized)
// ----------------------------------------------------------------
__global__ void __launch_bounds__(256) out_kernel(
    const float* __restrict__ ao, const float* __restrict__ conf,
    float4* __restrict__ out)
{
    const int total = B_ * FULLN * E4;   // 6,303,744
    int i = blockIdx.x * blockDim.x + threadIdx.x;
    if (i >= total) return;
    int b = i / (FULLN * E4);
    int c4 = i % E4;
    float s = conf[b];
    float4 v = reinterpret_cast<const float4*>(ao)[b * E4 + c4];
    v.x *= s; v.y *= s; v.z *= s; v.w *= s;
    out[i] = v;
}

// ----------------------------------------------------------------
extern "C" void kernel_launch(void* const* d_in, const int* in_sizes, int n_in,
                              void* d_out, int out_size)
{
    const float* x    = (const float*)d_in[0];
    const float* bio  = (const float*)d_in[1];
    const float* base = (const float*)d_in[2];
    const float* off  = (const float*)d_in[3];
    const float* conf = (const float*)d_in[4];
    const float* Ws   = (const float*)d_in[5];
    const float* bs   = (const float*)d_in[6];
    const float* Win  = (const float*)d_in[7];
    const float* bin  = (const float*)d_in[8];
    const float* Wo   = (const float*)d_in[9];
    const float* bo   = (const float*)d_in[10];
    float* out = (float*)d_out;

    float *sampled, *q, *T, *TK, *attn, *US, *U, *ctx, *ao;
    cudaGetSymbolAddress((void**)&sampled, g_sampled);
    cudaGetSymbolAddress((void**)&q,   g_q);
    cudaGetSymbolAddress((void**)&T,   g_T);
    cudaGetSymbolAddress((void**)&TK,  g_TK);
    cudaGetSymbolAddress((void**)&attn,g_attn);
    cudaGetSymbolAddress((void**)&US,  g_US);
    cudaGetSymbolAddress((void**)&U,   g_U);
    cudaGetSymbolAddress((void**)&ctx, g_ctx);
    cudaGetSymbolAddress((void**)&ao,  g_ao);

    // 1) trilinear sample -> sampled (2048, 768)
    sample_kernel<<<B_ * NB, 192>>>(x, base, off, sampled);

    // 2) q = bio @ Wq.T + bq   (64,768,768) NT
    sgemm_kernel<true><<<dim3(12, 1, 1), 256>>>(
        bio, Win, bin, q, 64, E_, E_, E_, E_, E_, 0, 0, 0, 0);

    // 3) T_h = q_h @ Wk_h  (per head; 64x768x64) NN, z = h
    sgemm_kernel<false><<<dim3(12, 1, H_), 256>>>(
        q, Win + E_ * E_, nullptr, T, 64, E_, HD,
        E_, E_, H_ * E_, HD, HD * E_, E_, 0);

    // 4) TK = T @ Ws   (768^3) NN
    sgemm_kernel<false><<<dim3(12, 12, 1), 256>>>(
        T, Ws, nullptr, TK, BH, E_, E_, E_, E_, E_, 0, 0, 0, 0);

    // 5) scores + softmax -> attn (768, 32)
    scores_softmax_kernel<<<BH, 128>>>(TK, T, q, sampled, bin, bs, attn);

    // 6) US[bh] = sum_p attn * sampled
    us_kernel<<<BH, 192>>>(attn, sampled, US);

    // 7) U = US @ Ws.T + bs   (768^3) NT
    sgemm_kernel<true><<<dim3(12, 12, 1), 256>>>(
        US, Ws, bs, U, BH, E_, E_, E_, E_, E_, 0, 0, 0, 0);

    // 8) ctx_h = U_h @ Wv_h.T + bv_h  (64x64x768) NT, z = h
    sgemm_kernel<true><<<dim3(1, 1, H_), 256>>>(
        U, Win + 2 * E_ * E_, bin + 2 * E_, ctx, 64, HD, E_,
        H_ * E_, E_, E_, E_, HD * E_, HD, HD);

    // 9) attn_out = ctx @ Wo.T + bo  (64,768,768) NT
    sgemm_kernel<true><<<dim3(12, 1, 1), 256>>>(
        ctx, Wo, bo, ao, 64, E_, E_, E_, E_, E_, 0, 0, 0, 0);

    // 10) broadcast * confidence -> out (64,513,768)
    out_kernel<<<(B_ * FULLN * E4 + 255) / 256, 256>>>(ao, conf, (float4*)out);
}

// round 2
// speedup vs baseline: 2.3350x; 2.3350x over previous
#include <cuda_runtime.h>
#include <math.h>

#define B_   64
#define FULLN 513
#define E_   768
#define NB   32
#define H_   12
#define HD   64
#define BH   (B_ * H_)        // 768
#define E4   (E_ / 4)         // 192

// -------- scratch (device globals; no allocation allowed) --------
__device__ float g_sampled[B_ * NB * E_];   // (2048, 768)
__device__ float g_q[B_ * E_];              // (64, 768)
__device__ float g_T[BH * E_];              // (768, 768)  row = b*12+h
__device__ float g_TK[BH * E_];             // (768, 768)
__device__ float g_attn[BH * NB];           // (768, 32)
__device__ float g_US[BH * E_];             // (768, 768)
__device__ float g_U[BH * E_];              // (768, 768)
__device__ float g_ctx[B_ * E_];            // (64, 768)
__device__ float g_ao[B_ * E_];             // (64, 768)
__device__ float g_part[4 * BH * E_];       // split-K partials (max 4 x 768x768)

// ----------------------------------------------------------------
// Trilinear border sample: one block per (b,p); 192 threads, float4 channels
// ----------------------------------------------------------------
__global__ void __launch_bounds__(192) sample_kernel(
    const float* __restrict__ x, const float* __restrict__ base,
    const float* __restrict__ off, float* __restrict__ out)
{
    int bp = blockIdx.x;
    int b = bp >> 5, p = bp & 31;

    float cx = fminf(fmaxf(base[p * 3 + 0] + off[bp * 3 + 0], -1.f), 1.f);
    float cy = fminf(fmaxf(base[p * 3 + 1] + off[bp * 3 + 1], -1.f), 1.f);
    float cz = fminf(fmaxf(base[p * 3 + 2] + off[bp * 3 + 2], -1.f), 1.f);

    float ix = (cx + 1.f) * 3.5f;   // (W-1)=7
    float iy = (cy + 1.f) * 3.5f;
    float iz = (cz + 1.f) * 3.5f;
    float fx = floorf(ix), fy = floorf(iy), fz = floorf(iz);
    float wx = ix - fx, wy = iy - fy, wz = iz - fz;
    int x0 = max(0, min(7, (int)fx));
    int y0 = max(0, min(7, (int)fy));
    int z0 = max(0, min(7, (int)fz));
    int x1 = min(7, x0 + 1), y1 = min(7, y0 + 1), z1 = min(7, z0 + 1);

    int r000 = 1 + ((z0 * 8 + y0) * 8 + x0);
    int r001 = 1 + ((z0 * 8 + y0) * 8 + x1);
    int r010 = 1 + ((z0 * 8 + y1) * 8 + x0);
    int r011 = 1 + ((z0 * 8 + y1) * 8 + x1);
    int r100 = 1 + ((z1 * 8 + y0) * 8 + x0);
    int r101 = 1 + ((z1 * 8 + y0) * 8 + x1);
    int r110 = 1 + ((z1 * 8 + y1) * 8 + x0);
    int r111 = 1 + ((z1 * 8 + y1) * 8 + x1);

    float w000 = (1.f - wz) * (1.f - wy) * (1.f - wx);
    float w001 = (1.f - wz) * (1.f - wy) * wx;
    float w010 = (1.f - wz) * wy * (1.f - wx);
    float w011 = (1.f - wz) * wy * wx;
    float w100 = wz * (1.f - wy) * (1.f - wx);
    float w101 = wz * (1.f - wy) * wx;
    float w110 = wz * wy * (1.f - wx);
    float w111 = wz * wy * wx;

    const float4* X = reinterpret_cast<const float4*>(x) + (long)b * FULLN * E4;
    int t = threadIdx.x;
    float4 s = make_float4(0.f, 0.f, 0.f, 0.f);
#define ACC(R, W) { float4 v = X[(R) * E4 + t]; \
        s.x = fmaf(W, v.x, s.x); s.y = fmaf(W, v.y, s.y); \
        s.z = fmaf(W, v.z, s.z); s.w = fmaf(W, v.w, s.w); }
    ACC(r000, w000) ACC(r001, w001) ACC(r010, w010) ACC(r011, w011)
    ACC(r100, w100) ACC(r101, w101) ACC(r110, w110) ACC(r111, w111)
#undef ACC
    reinterpret_cast<float4*>(out)[(long)bp * E4 + t] = s;
}

// ----------------------------------------------------------------
// Generic fp32 GEMM with split-K.
// C[m,n] = sum_k A[m,k] * (TB ? B[n,k] : B[k,n])  (bias only if nSplit==1)
// 64x64 tile, 256 threads, 4x4 per thread, K step 16.
// blockIdx.z = zb * nSplit + sp; split sp handles K-range [sp*kChunk, (sp+1)*kChunk).
// For nSplit>1, C is a partial buffer; writes go to C + sp*sCsplit.
// All dims are multiples of the tile sizes; no bounds checks.
// ----------------------------------------------------------------
template <bool TB>
__global__ void __launch_bounds__(256) sgemm_kernel(
    const float* __restrict__ A, const float* __restrict__ Bm,
    const float* __restrict__ bias, float* __restrict__ C,
    int kChunk, int lda, int ldb, int ldc,
    int sAz, int sBz, int sCz, int sBiasz,
    int nSplit, long sCsplit)
{
    __shared__ __align__(16) float As[16][68];
    __shared__ __align__(16) float Bs[16][68];
    const int tid = threadIdx.x;
    const int m0 = blockIdx.y * 64;
    const int n0 = blockIdx.x * 64;

    const int zb = blockIdx.z / nSplit;
    const int sp = blockIdx.z - zb * nSplit;

    A  += (long)zb * sAz + sp * kChunk;
    if (TB) Bm += (long)zb * sBz + sp * kChunk;
    else    Bm += (long)zb * sBz + (long)sp * kChunk * ldb;
    C  += (long)zb * sCz + (long)sp * sCsplit;
    const int biasOff = zb * sBiasz;

    const int ra = tid >> 2;          // 0..63
    const int ka = (tid & 3) << 2;    // 0,4,8,12
    const int ty = tid >> 4;          // 0..15
    const int tx = tid & 15;          // 0..15

    float acc[4][4];
#pragma unroll
    for (int i = 0; i < 4; i++)
#pragma unroll
        for (int j = 0; j < 4; j++) acc[i][j] = 0.f;

    for (int k0 = 0; k0 < kChunk; k0 += 16) {
        float4 a4 = *reinterpret_cast<const float4*>(&A[(long)(m0 + ra) * lda + k0 + ka]);
        As[ka + 0][ra] = a4.x; As[ka + 1][ra] = a4.y;
        As[ka + 2][ra] = a4.z; As[ka + 3][ra] = a4.w;
        if (TB) {
            float4 b4 = *reinterpret_cast<const float4*>(&Bm[(long)(n0 + ra) * ldb + k0 + ka]);
            Bs[ka + 0][ra] = b4.x; Bs[ka + 1][ra] = b4.y;
            Bs[ka + 2][ra] = b4.z; Bs[ka + 3][ra] = b4.w;
        } else {
            const int kb = tid >> 4;          // 0..15
            const int nb = (tid & 15) << 2;   // 0..60
            float4 b4 = *reinterpret_cast<const float4*>(&Bm[(long)(k0 + kb) * ldb + n0 + nb]);
            Bs[kb][nb + 0] = b4.x; Bs[kb][nb + 1] = b4.y;
            Bs[kb][nb + 2] = b4.z; Bs[kb][nb + 3] = b4.w;
        }
        __syncthreads();
#pragma unroll
        for (int kk = 0; kk < 16; kk++) {
            float4 av = *reinterpret_cast<const float4*>(&As[kk][ty * 4]);
            float4 bv = *reinterpret_cast<const float4*>(&Bs[kk][tx * 4]);
            float a[4] = {av.x, av.y, av.z, av.w};
            float b[4] = {bv.x, bv.y, bv.z, bv.w};
#pragma unroll
            for (int i = 0; i < 4; i++)
#pragma unroll
                for (int j = 0; j < 4; j++)
                    acc[i][j] = fmaf(a[i], b[j], acc[i][j]);
        }
        __syncthreads();
    }

#pragma unroll
    for (int i = 0; i < 4; i++) {
        int m = m0 + ty * 4 + i;
#pragma unroll
        for (int j = 0; j < 4; j++) {
            int n = n0 + tx * 4 + j;
            float v = acc[i][j];
            if (nSplit == 1 && bias) v += bias[biasOff + n];
            C[(long)m * ldc + n] = v;
        }
    }
}

// ----------------------------------------------------------------
// Split-K reduce: C[i] = sum_sp part[sp*total + i] + bias[i % ldc]
// float4-vectorized; total4 = total/4, ldc4 = ldc/4.
// ----------------------------------------------------------------
__global__ void __launch_bounds__(256) reduce_kernel(
    const float* __restrict__ part, const float* __restrict__ bias,
    float* __restrict__ C, int total4, int nSplit, int ldc4)
{
    int i = blockIdx.x * blockDim.x + threadIdx.x;
    if (i >= total4) return;
    const float4* P = reinterpret_cast<const float4*>(part);
    float4 s = P[i];
    for (int sp = 1; sp < nSplit; sp++) {
        float4 v = P[(long)sp * total4 + i];
        s.x += v.x; s.y += v.y; s.z += v.z; s.w += v.w;
    }
    if (bias) {
        float4 b = reinterpret_cast<const float4*>(bias)[i % ldc4];
        s.x += b.x; s.y += b.y; s.z += b.z; s.w += b.w;
    }
    reinterpret_cast<float4*>(C)[i] = s;
}

// ----------------------------------------------------------------
// scores + softmax per (b,h)
// ----------------------------------------------------------------
__global__ void __launch_bounds__(128) scores_softmax_kernel(
    const float* __restrict__ TK, const float* __restrict__ T,
    const float* __restrict__ q, const float* __restrict__ sampled,
    const float* __restrict__ in_proj_b, const float* __restrict__ bs,
    float* __restrict__ attn)
{
    int bh = blockIdx.x;
    int b = bh / H_, h = bh % H_;
    __shared__ float tk[E_];
    __shared__ float sc[NB];
    __shared__ float red[4];
    __shared__ float cbs;
    int tid = threadIdx.x;
    int w = tid >> 5, lane = tid & 31;

    const float* TKrow = TK + (long)bh * E_;
    const float* Trow  = T + (long)bh * E_;
    float part = 0.f;
    for (int f = tid; f < E_; f += 128) {
        float t = TKrow[f];
        tk[f] = t;
        part += Trow[f] * bs[f];
    }
    if (tid < HD)
        part += q[(long)b * E_ + h * HD + tid] * in_proj_b[E_ + h * HD + tid];
#pragma unroll
    for (int o = 16; o; o >>= 1) part += __shfl_xor_sync(0xffffffffu, part, o);
    if (lane == 0) red[w] = part;
    __syncthreads();
    if (tid == 0) cbs = red[0] + red[1] + red[2] + red[3];
    __syncthreads();

    float cb = cbs;
#pragma unroll
    for (int pi = 0; pi < 8; pi++) {
        int p = w * 8 + pi;
        const float* srow = sampled + ((long)b * NB + p) * E_;
        float d = 0.f;
        for (int f = lane; f < E_; f += 32) d = fmaf(tk[f], srow[f], d);
#pragma unroll
        for (int o = 16; o; o >>= 1) d += __shfl_xor_sync(0xffffffffu, d, o);
        if (lane == 0) sc[p] = (d + cb) * 0.125f;
    }
    __syncthreads();
    if (tid < NB) {
        float s = sc[tid];
        float m = s;
#pragma unroll
        for (int o = 16; o; o >>= 1) m = fmaxf(m, __shfl_xor_sync(0xffffffffu, m, o));
        float e = expf(s - m);
        float sum = e;
#pragma unroll
        for (int o = 16; o; o >>= 1) sum += __shfl_xor_sync(0xffffffffu, sum, o);
        attn[(long)bh * NB + tid] = e / sum;
    }
}

// ----------------------------------------------------------------
// US[bh, f] = sum_p attn[bh,p] * sampled[b,p,f]
// ----------------------------------------------------------------
__global__ void __launch_bounds__(192) us_kernel(
    const float* __restrict__ attn, const float* __restrict__ sampled,
    float* __restrict__ US)
{
    int bh = blockIdx.x;
    int b = bh / H_;
    __shared__ float a[NB];
    if (threadIdx.x < NB) a[threadIdx.x] = attn[(long)bh * NB + threadIdx.x];
    __syncthreads();
    int t = threadIdx.x;
    const float4* S = reinterpret_cast<const float4*>(sampled) + (long)b * NB * E4;
    float4 acc = make_float4(0.f, 0.f, 0.f, 0.f);
#pragma unroll 8
    for (int p = 0; p < NB; p++) {
        float wv = a[p];
        float4 s = S[p * E4 + t];
        acc.x = fmaf(wv, s.x, acc.x); acc.y = fmaf(wv, s.y, acc.y);
        acc.z = fmaf(wv, s.z, acc.z); acc.w = fmaf(wv, s.w, acc.w);
    }
    reinterpret_cast<float4*>(US)[(long)bh * E4 + t] = acc;
}

// ----------------------------------------------------------------
// out[b,n,c] = attn_out[b,c] * confidence[b]
// ----------------------------------------------------------------
__global__ void __launch_bounds__(256) out_kernel(
    const float* __restrict__ ao, const float* __restrict__ conf,
    float4* __restrict__ out)
{
    const int total = B_ * FULLN * E4;   // 6,303,744
    int i = blockIdx.x * blockDim.x + threadIdx.x;
    if (i >= total) return;
    int b = i / (FULLN * E4);
    int c4 = i % E4;
    float s = conf[b];
    float4 v = reinterpret_cast<const float4*>(ao)[b * E4 + c4];
    v.x *= s; v.y *= s; v.z *= s; v.w *= s;
    out[i] = v;
}

// ----------------------------------------------------------------
extern "C" void kernel_launch(void* const* d_in, const int* in_sizes, int n_in,
                              void* d_out, int out_size)
{
    const float* x    = (const float*)d_in[0];
    const float* bio  = (const float*)d_in[1];
    const float* base = (const float*)d_in[2];
    const float* off  = (const float*)d_in[3];
    const float* conf = (const float*)d_in[4];
    const float* Ws   = (const float*)d_in[5];
    const float* bs   = (const float*)d_in[6];
    const float* Win  = (const float*)d_in[7];
    const float* bin  = (const float*)d_in[8];
    const float* Wo   = (const float*)d_in[9];
    const float* bo   = (const float*)d_in[10];
    float* out = (float*)d_out;

    float *sampled, *q, *T, *TK, *attn, *US, *U, *ctx, *ao, *part;
    cudaGetSymbolAddress((void**)&sampled, g_sampled);
    cudaGetSymbolAddress((void**)&q,   g_q);
    cudaGetSymbolAddress((void**)&T,   g_T);
    cudaGetSymbolAddress((void**)&TK,  g_TK);
    cudaGetSymbolAddress((void**)&attn,g_attn);
    cudaGetSymbolAddress((void**)&US,  g_US);
    cudaGetSymbolAddress((void**)&U,   g_U);
    cudaGetSymbolAddress((void**)&ctx, g_ctx);
    cudaGetSymbolAddress((void**)&ao,  g_ao);
    cudaGetSymbolAddress((void**)&part,g_part);

    const int smallT4 = 64 * E_ / 4;    // 12288
    const int bigT4   = BH * E_ / 4;    // 147456

    // 1) trilinear sample -> sampled (2048, 768)
    sample_kernel<<<B_ * NB, 192>>>(x, base, off, sampled);

    // 2) q = bio @ Wq.T + bq  (64x768x768) NT, split-K=8
    sgemm_kernel<true><<<dim3(12, 1, 8), 256>>>(
        bio, Win, nullptr, part, 96, E_, E_, E_, 0, 0, 0, 0, 8, (long)64 * E_);
    reduce_kernel<<<(smallT4 + 255) / 256, 256>>>(part, bin, q, smallT4, 8, E4);

    // 3) T_h = q_h @ Wk_h  (per head; 64x768x64) NN, z = h (no split, K=64)
    sgemm_kernel<false><<<dim3(12, 1, H_), 256>>>(
        q, Win + E_ * E_, nullptr, T, HD,
        E_, E_, H_ * E_, HD, HD * E_, E_, 0, 1, 0);

    // 4) TK = T @ Ws   (768^3) NN, split-K=4
    sgemm_kernel<false><<<dim3(12, 12, 4), 256>>>(
        T, Ws, nullptr, part, 192, E_, E_, E_, 0, 0, 0, 0, 4, (long)BH * E_);
    reduce_kernel<<<(bigT4 + 255) / 256, 256>>>(part, nullptr, TK, bigT4, 4, E4);

    // 5) scores + softmax -> attn (768, 32)
    scores_softmax_kernel<<<BH, 128>>>(TK, T, q, sampled, bin, bs, attn);

    // 6) US[bh] = sum_p attn * sampled
    us_kernel<<<BH, 192>>>(attn, sampled, US);

    // 7) U = US @ Ws.T + bs   (768^3) NT, split-K=4
    sgemm_kernel<true><<<dim3(12, 12, 4), 256>>>(
        US, Ws, nullptr, part, 192, E_, E_, E_, 0, 0, 0, 0, 4, (long)BH * E_);
    reduce_kernel<<<(bigT4 + 255) / 256, 256>>>(part, bs, U, bigT4, 4, E4);

    // 8) ctx_h = U_h @ Wv_h.T + bv_h  (64x64x768) NT, z = h, split-K=8
    sgemm_kernel<true><<<dim3(1, 1, H_ * 8), 256>>>(
        U, Win + 2 * E_ * E_, nullptr, part, 96,
        H_ * E_, E_, E_, E_, HD * E_, HD, HD, 8, (long)64 * E_);
    reduce_kernel<<<(smallT4 + 255) / 256, 256>>>(part, bin + 2 * E_, ctx, smallT4, 8, E4);

    // 9) attn_out = ctx @ Wo.T + bo  (64x768x768) NT, split-K=8
    sgemm_kernel<true><<<dim3(12, 1, 8), 256>>>(
        ctx, Wo, nullptr, part, 96, E_, E_, E_, 0, 0, 0, 0, 8, (long)64 * E_);
    reduce_kernel<<<(smallT4 + 255) / 256, 256>>>(part, bo, ao, smallT4, 8, E4);

    // 10) broadcast * confidence -> out (64,513,768)
    out_kernel<<<(B_ * FULLN * E4 + 255) / 256, 256>>>(ao, conf, (float4*)out);
}